// round 2
// baseline (speedup 1.0000x reference)
#include <cuda_runtime.h>
#include <math.h>
#include <stdint.h>

#define NBATCH 64
#define LSEQ   2048
#define HDIM   512

// ======================================================================
// Kernel 1: Xh[m, j] = sum_k emb[X[m]][k] * W_xh[j][k] + b_xh[j]
// written into d_out (which the scan kernel then overwrites in place
// with h_t, consuming xh_t and h_{t-1} from the same array).
// 64x64 tile, BK=16, 256 threads, 4x4 register tile.
// ======================================================================
__global__ __launch_bounds__(256) void xh_gemm_kernel(
    const int* __restrict__ X, const float* __restrict__ emb,
    const float* __restrict__ W_xh, const float* __restrict__ b_xh,
    float* __restrict__ out)
{
    __shared__ float As[16][64];
    __shared__ float Bs[16][64];
    const int tid = threadIdx.x;
    const int m0 = blockIdx.y * 64;
    const int j0 = blockIdx.x * 64;
    const int row = tid >> 2;   // 0..63 (tile row for loading)
    const int kq  = tid & 3;    // 0..3  (k quad for loading)
    const int ty  = tid >> 4;   // 0..15 (compute row group)
    const int tx  = tid & 15;   // 0..15 (compute col group)

    const int tok = X[m0 + row];
    const float* arow = emb  + (size_t)tok        * HDIM + kq * 4;
    const float* brow = W_xh + (size_t)(j0 + row) * HDIM + kq * 4;

    float acc[4][4];
#pragma unroll
    for (int i = 0; i < 4; i++)
#pragma unroll
        for (int j = 0; j < 4; j++) acc[i][j] = 0.f;

    for (int k0 = 0; k0 < HDIM; k0 += 16) {
        float4 av = *(const float4*)(arow + k0);
        float4 bv = *(const float4*)(brow + k0);
        __syncthreads();
        As[kq*4+0][row] = av.x; As[kq*4+1][row] = av.y;
        As[kq*4+2][row] = av.z; As[kq*4+3][row] = av.w;
        Bs[kq*4+0][row] = bv.x; Bs[kq*4+1][row] = bv.y;
        Bs[kq*4+2][row] = bv.z; Bs[kq*4+3][row] = bv.w;
        __syncthreads();
#pragma unroll
        for (int kk = 0; kk < 16; kk++) {
            float4 a = *(const float4*)(&As[kk][ty*4]);
            float4 b = *(const float4*)(&Bs[kk][tx*4]);
            acc[0][0] = fmaf(a.x, b.x, acc[0][0]);
            acc[0][1] = fmaf(a.x, b.y, acc[0][1]);
            acc[0][2] = fmaf(a.x, b.z, acc[0][2]);
            acc[0][3] = fmaf(a.x, b.w, acc[0][3]);
            acc[1][0] = fmaf(a.y, b.x, acc[1][0]);
            acc[1][1] = fmaf(a.y, b.y, acc[1][1]);
            acc[1][2] = fmaf(a.y, b.z, acc[1][2]);
            acc[1][3] = fmaf(a.y, b.w, acc[1][3]);
            acc[2][0] = fmaf(a.z, b.x, acc[2][0]);
            acc[2][1] = fmaf(a.z, b.y, acc[2][1]);
            acc[2][2] = fmaf(a.z, b.z, acc[2][2]);
            acc[2][3] = fmaf(a.z, b.w, acc[2][3]);
            acc[3][0] = fmaf(a.w, b.x, acc[3][0]);
            acc[3][1] = fmaf(a.w, b.y, acc[3][1]);
            acc[3][2] = fmaf(a.w, b.z, acc[3][2]);
            acc[3][3] = fmaf(a.w, b.w, acc[3][3]);
        }
    }

    float4 bx = *(const float4*)(b_xh + j0 + tx*4);
#pragma unroll
    for (int i = 0; i < 4; i++) {
        float4 v;
        v.x = acc[i][0] + bx.x;
        v.y = acc[i][1] + bx.y;
        v.z = acc[i][2] + bx.z;
        v.w = acc[i][3] + bx.w;
        *(float4*)(out + (size_t)(m0 + ty*4 + i) * HDIM + j0 + tx*4) = v;
    }
}

// ======================================================================
// Kernel 2: persistent scan over 2048 timesteps.
// Grid = 128 CTAs (8 batch-groups x 16 j-groups), 128 threads (4 warps,
// exactly one per SMSP). Each CTA holds its 32-row W_hh slice in smem
// for the whole kernel. Per step: stage h_{t-1} slice (8 rows) into
// smem, compute 8x32 outputs via 4x4 register tiles with 8-way K-split,
// smem-reduce the K partials, add bias + xh (read in place from out),
// tanh, write h_t back into out, grid-barrier.
// ======================================================================
#define G_SCAN 128
#define T_SCAN 128
#define NB 8
#define JB 32

// smem layout (float offsets)
#define OFF_W 0                       // 32*512   = 16384 floats
#define OFF_H (JB*HDIM)               // + 8*512  -> 20480
#define OFF_R (OFF_H + NB*HDIM)       // + 8*256  -> 22528
#define OFF_B (OFF_R + 8*NB*JB)       // + 32     -> 22560
#define SMEM_FLOATS (OFF_B + JB)
#define SMEM_BYTES (SMEM_FLOATS * 4)  // 90240 B

__device__ unsigned int g_bar_count = 0;
__device__ volatile unsigned int g_bar_phase = 0;

// XOR swizzles (float4 granularity, row stride = 128 float4s) to break
// the stride-512 bank alignment of W/h rows.
__device__ __forceinline__ int wsw(int r, int k4) { return r*128 + (k4 ^ ((r>>2)&7)); }
__device__ __forceinline__ int hsw(int r, int k4) { return r*128 + (k4 ^ ((r>>2)&1)); }

__global__ __launch_bounds__(T_SCAN, 1) void scan_kernel(
    const float* __restrict__ W_hh, const float* __restrict__ b_hh, float* out)
{
    extern __shared__ float sm[];
    float4* smW4 = (float4*)(sm + OFF_W);
    float4* smH4 = (float4*)(sm + OFF_H);
    const int tid = threadIdx.x;
    const int gn = blockIdx.x >> 4;    // 0..7
    const int gj = blockIdx.x & 15;    // 0..15
    const int n0 = gn * NB;
    const int j0 = gj * JB;

    // phase base: read BEFORE any barrier can complete (all CTAs must
    // arrive first), so this is race-free and replay-deterministic.
    unsigned int local_phase = 0;
    if (tid == 0) local_phase = g_bar_phase;

    // load persistent W_hh slice (rows j0..j0+31), swizzled
    const float4* W4 = (const float4*)W_hh + (size_t)j0 * (HDIM/4);
    for (int i = tid; i < JB * (HDIM/4); i += T_SCAN) {
        int r = i >> 7, c4 = i & 127;
        smW4[wsw(r, c4)] = W4[i];
    }
    if (tid < JB) sm[OFF_B + tid] = b_hh[j0 + tid];

    // compute-thread mapping: 8 k-chunks x 8 j-tiles x 2 n-tiles = 128
    const int kc  = tid >> 4;          // 0..7  k-chunk (64 k each)
    const int jt  = (tid >> 1) & 7;    // 0..7  j-tile (4 j each)
    const int nt  = tid & 1;           // 0..1  n-tile (4 n each)
    const int nt4 = nt * 4, jt4 = jt * 4;
    const int kb4 = kc * 16;           // float4 base within row

    float4* out4 = (float4*)out;

    for (int t = 0; t < LSEQ; t++) {
        // ---- stage h_{t-1} (8 rows x 512) ----
        if (t == 0) {
            float4 z = make_float4(0.f, 0.f, 0.f, 0.f);
            for (int i = tid; i < NB * 128; i += T_SCAN) {
                int r = i >> 7, c4 = i & 127;
                smH4[hsw(r, c4)] = z;
            }
        } else {
            for (int i = tid; i < NB * 128; i += T_SCAN) {
                int r = i >> 7, c4 = i & 127;
                // L2-only load: other CTAs wrote this, L1 would be stale-risk
                smH4[hsw(r, c4)] =
                    __ldcg(&out4[((size_t)(n0 + r) * LSEQ + (t - 1)) * 128 + c4]);
            }
        }
        __syncthreads();

        // ---- partial GEMM: acc[4n][4j] over this thread's 64-k chunk ----
        float acc[4][4];
#pragma unroll
        for (int a = 0; a < 4; a++)
#pragma unroll
            for (int b = 0; b < 4; b++) acc[a][b] = 0.f;

#pragma unroll 4
        for (int s = 0; s < 16; s++) {
            float4 hv[4], wv[4];
#pragma unroll
            for (int i = 0; i < 4; i++) hv[i] = smH4[hsw(nt4 + i, kb4 + s)];
#pragma unroll
            for (int i = 0; i < 4; i++) wv[i] = smW4[wsw(jt4 + i, kb4 + s)];
#pragma unroll
            for (int a = 0; a < 4; a++)
#pragma unroll
                for (int b = 0; b < 4; b++) {
                    acc[a][b] = fmaf(hv[a].x, wv[b].x, acc[a][b]);
                    acc[a][b] = fmaf(hv[a].y, wv[b].y, acc[a][b]);
                    acc[a][b] = fmaf(hv[a].z, wv[b].z, acc[a][b]);
                    acc[a][b] = fmaf(hv[a].w, wv[b].w, acc[a][b]);
                }
        }

        // ---- write K-split partials ----
        float* rp = sm + OFF_R + kc * (NB * JB);
#pragma unroll
        for (int a = 0; a < 4; a++)
#pragma unroll
            for (int b = 0; b < 4; b++)
                rp[(nt4 + a) * JB + (jt4 + b)] = acc[a][b];
        __syncthreads();

        // ---- reduce + bias + xh + tanh + store h_t ----
        for (int o = tid; o < NB * JB; o += T_SCAN) {   // 2 iterations
            int nn = o >> 5, jj = o & 31;
            float s = 0.f;
#pragma unroll
            for (int c = 0; c < 8; c++) s += sm[OFF_R + c * (NB * JB) + o];
            size_t oi = ((size_t)(n0 + nn) * LSEQ + t) * HDIM + j0 + jj;
            out[oi] = tanhf(s + sm[OFF_B + jj] + out[oi]);
        }

        // ---- grid barrier (sense via monotonically increasing phase) ----
        __threadfence();   // publish our h_t writes before arriving
        __syncthreads();
        if (tid == 0) {
            unsigned int target = ++local_phase;
            unsigned int old = atomicInc(&g_bar_count, G_SCAN - 1);
            if (old == G_SCAN - 1) {
                g_bar_phase = target;       // last arrival releases
            } else {
                while (g_bar_phase != target) { }
            }
        }
        __syncthreads();
    }
}

// ======================================================================
extern "C" void kernel_launch(void* const* d_in, const int* in_sizes, int n_in,
                              void* d_out, int out_size) {
    const int*   X    = (const int*)d_in[0];
    const float* emb  = (const float*)d_in[1];
    const float* W_hh = (const float*)d_in[2];
    const float* b_hh = (const float*)d_in[3];
    const float* W_xh = (const float*)d_in[4];
    const float* b_xh = (const float*)d_in[5];
    float* out = (float*)d_out;

    (void)in_sizes; (void)n_in; (void)out_size;

    cudaFuncSetAttribute(scan_kernel,
                         cudaFuncAttributeMaxDynamicSharedMemorySize, SMEM_BYTES);

    dim3 g1(HDIM / 64, (NBATCH * LSEQ) / 64);   // (8, 2048)
    xh_gemm_kernel<<<g1, 256>>>(X, emb, W_xh, b_xh, out);

    scan_kernel<<<G_SCAN, T_SCAN, SMEM_BYTES>>>(W_hh, b_hh, out);
}

// round 4
// speedup vs baseline: 1.0560x; 1.0560x over previous
#include <cuda_runtime.h>
#include <math.h>
#include <stdint.h>

#define NBATCH 64
#define LSEQ   2048
#define HDIM   512

typedef unsigned long long u64;

// ---------------------------------------------------------------- helpers
__device__ __forceinline__ void ffma2(u64 &acc, u64 a, u64 b) {
    asm("fma.rn.f32x2 %0, %1, %2, %0;" : "+l"(acc) : "l"(a), "l"(b));
}
__device__ __forceinline__ void lds_v2u64(u64 &a, u64 &b, unsigned addr) {
    asm volatile("ld.shared.v2.b64 {%0,%1}, [%2];" : "=l"(a), "=l"(b) : "r"(addr));
}
__device__ __forceinline__ float hsum2(u64 v) {
    float x, y;
    asm("mov.b64 {%0,%1}, %2;" : "=f"(x), "=f"(y) : "l"(v));
    return x + y;
}
__device__ __forceinline__ unsigned smem_u32(const void* p) {
    unsigned r;
    asm("{ .reg .u64 t; cvta.to.shared.u64 t, %1; cvt.u32.u64 %0, t; }"
        : "=r"(r) : "l"(p));
    return r;
}
__device__ __forceinline__ void st_cluster_f32(unsigned addr, int rank, float v) {
    unsigned ra;
    asm volatile("mapa.shared::cluster.u32 %0, %1, %2;" : "=r"(ra) : "r"(addr), "r"(rank));
    asm volatile("st.shared::cluster.f32 [%0], %1;" :: "r"(ra), "f"(v) : "memory");
}
#define CLUSTER_SYNC() do { \
    asm volatile("barrier.cluster.arrive.aligned;" ::: "memory"); \
    asm volatile("barrier.cluster.wait.aligned;"   ::: "memory"); } while (0)

// ======================================================================
// Kernel 1: Xh = emb[X] @ W_xh^T + b_xh  -> out (in place for the scan)
// 64x64 tile, BK=16, 256 threads, 4x4 per-thread tile, f32x2 packed FMA.
// Smem stores k-PAIRS (float2) so packed operands load via ld.shared.v2.b64.
// ======================================================================
__global__ __launch_bounds__(256) void xh_gemm_kernel(
    const int* __restrict__ X, const float* __restrict__ emb,
    const float* __restrict__ W_xh, const float* __restrict__ b_xh,
    float* __restrict__ out)
{
    __shared__ __align__(16) float2 As2[8][64];   // [k-pair][row]
    __shared__ __align__(16) float2 Bs2[8][64];
    const int tid = threadIdx.x;
    const int m0 = blockIdx.y * 64;
    const int j0 = blockIdx.x * 64;
    const int row = tid >> 2;   // 0..63
    const int kq  = tid & 3;    // 0..3
    const int ty  = tid >> 4;   // 0..15
    const int tx  = tid & 15;   // 0..15

    const int tok = X[m0 + row];
    const float* arow = emb  + (size_t)tok        * HDIM + kq * 4;
    const float* brow = W_xh + (size_t)(j0 + row) * HDIM + kq * 4;

    const unsigned aB = smem_u32(As2);
    const unsigned bB = smem_u32(Bs2);

    u64 acc[4][4];
#pragma unroll
    for (int i = 0; i < 4; i++)
#pragma unroll
        for (int j = 0; j < 4; j++) acc[i][j] = 0ull;

    float4 av = *(const float4*)(arow);
    float4 bv = *(const float4*)(brow);

    for (int k0 = 0; k0 < HDIM; k0 += 16) {
        __syncthreads();
        As2[kq*2+0][row] = make_float2(av.x, av.y);
        As2[kq*2+1][row] = make_float2(av.z, av.w);
        Bs2[kq*2+0][row] = make_float2(bv.x, bv.y);
        Bs2[kq*2+1][row] = make_float2(bv.z, bv.w);
        __syncthreads();
        if (k0 + 16 < HDIM) {
            av = *(const float4*)(arow + k0 + 16);
            bv = *(const float4*)(brow + k0 + 16);
        }
#pragma unroll
        for (int kk2 = 0; kk2 < 8; kk2++) {
            u64 a0,a1,a2_,a3_, b0,b1,b2_,b3_;
            lds_v2u64(a0,  a1,  aB + (unsigned)(kk2*64 + ty*4    )*8);
            lds_v2u64(a2_, a3_, aB + (unsigned)(kk2*64 + ty*4 + 2)*8);
            lds_v2u64(b0,  b1,  bB + (unsigned)(kk2*64 + tx*4    )*8);
            lds_v2u64(b2_, b3_, bB + (unsigned)(kk2*64 + tx*4 + 2)*8);
            ffma2(acc[0][0], a0,  b0);  ffma2(acc[0][1], a0,  b1);
            ffma2(acc[0][2], a0,  b2_); ffma2(acc[0][3], a0,  b3_);
            ffma2(acc[1][0], a1,  b0);  ffma2(acc[1][1], a1,  b1);
            ffma2(acc[1][2], a1,  b2_); ffma2(acc[1][3], a1,  b3_);
            ffma2(acc[2][0], a2_, b0);  ffma2(acc[2][1], a2_, b1);
            ffma2(acc[2][2], a2_, b2_); ffma2(acc[2][3], a2_, b3_);
            ffma2(acc[3][0], a3_, b0);  ffma2(acc[3][1], a3_, b1);
            ffma2(acc[3][2], a3_, b2_); ffma2(acc[3][3], a3_, b3_);
        }
    }

    float4 bx = *(const float4*)(b_xh + j0 + tx*4);
#pragma unroll
    for (int i = 0; i < 4; i++) {
        float4 v;
        v.x = hsum2(acc[i][0]) + bx.x;
        v.y = hsum2(acc[i][1]) + bx.y;
        v.z = hsum2(acc[i][2]) + bx.z;
        v.w = hsum2(acc[i][3]) + bx.w;
        *(float4*)(out + (size_t)(m0 + ty*4 + i) * HDIM + j0 + tx*4) = v;
    }
}

// ======================================================================
// Kernel 2: persistent scan. 16 independent batch-groups (NB=4 rows each),
// each group = one 8-CTA cluster over the j dimension (JB=64 per CTA).
// h exchange via DSMEM pushes + barrier.cluster — NO grid barrier, no
// __threadfence, no L2 h-roundtrip. Double-buffered h in smem.
// 128 threads: kc(8 k-chunks of 64) x jt(16 j-tiles of 4); 4x4 per-thread
// tile with f32x2 packed FMA (k-pairs).
// ======================================================================
#define CL   8
#define SNB  4
#define SJB  64
#define ST   128

// smem float offsets
#define SOFF_W   0                         // 64 rows x 512 = 32768 floats
#define SOFF_H0  32768                     // 4 x 512
#define SOFF_H1  (SOFF_H0 + SNB*HDIM)      // 4 x 512
#define SOFF_R   (SOFF_H1 + SNB*HDIM)      // 8 x 256 partials
#define SOFF_B   (SOFF_R + 8*SNB*SJB)      // 64 bias
#define SSMEM_FLOATS (SOFF_B + SJB)
#define SSMEM_BYTES  (SSMEM_FLOATS * 4)    // 155,904 B

// W smem swizzle at float4 granularity (row stride 128 float4)
__device__ __forceinline__ int wsw(int r, int k4) { return r*128 + (k4 ^ ((r>>2)&7)); }

__global__ __launch_bounds__(ST, 1) __cluster_dims__(CL, 1, 1)
void scan_kernel(const float* __restrict__ W_hh,
                 const float* __restrict__ b_hh, float* __restrict__ out)
{
    extern __shared__ float sm[];
    const unsigned smb = smem_u32(sm);
    const int tid = threadIdx.x;
    int rank;
    asm("mov.u32 %0, %%cluster_ctarank;" : "=r"(rank));
    const int gn = blockIdx.x / CL;        // 0..15 batch-group
    const int n0 = gn * SNB;
    const int j0 = rank * SJB;

    // persistent W_hh slice (rows j0..j0+63), swizzled
    const float4* W4 = (const float4*)W_hh + (size_t)j0 * (HDIM/4);
    float4* smW4 = (float4*)(sm + SOFF_W);
    for (int i = tid; i < SJB * (HDIM/4); i += ST) {
        int r = i >> 7, c4 = i & 127;
        smW4[wsw(r, c4)] = W4[i];
    }
    if (tid < SJB) sm[SOFF_B + tid] = b_hh[j0 + tid];
    for (int i = tid; i < SNB * HDIM; i += ST) sm[SOFF_H0 + i] = 0.f;  // h_{-1}=0
    __syncthreads();
    CLUSTER_SYNC();

    const int kc  = tid >> 4;              // 0..7
    const int jt  = tid & 15;              // 0..15
    const int kb4 = kc * 16;               // float4 base of this k-chunk
    const int xr  = jt & 7;                // swizzle xor for W rows jt*4..+3

    unsigned wRow[4];
#pragma unroll
    for (int i = 0; i < 4; i++)
        wRow[i] = smb + SOFF_W*4 + (unsigned)(jt*4 + i) * 2048;   // 128 f4 * 16B

    // reduce/output ownership: 2 outputs per thread
    const int o0 = tid, o1 = tid + ST;
    const int nn0 = o0 >> 6, jj0 = o0 & 63;
    const int nn1 = o1 >> 6, jj1 = o1 & 63;
    const size_t ob0 = (size_t)(n0 + nn0) * LSEQ * HDIM + j0 + jj0;
    const size_t ob1 = (size_t)(n0 + nn1) * LSEQ * HDIM + j0 + jj1;

    for (int t = 0; t < LSEQ; t++) {
        const unsigned hb = smb + (SOFF_H0 + (t & 1) * (SNB*HDIM)) * 4;       // read buf
        const unsigned pb = smb + (SOFF_H0 + ((t & 1) ^ 1) * (SNB*HDIM)) * 4; // push buf

        // prefetch xh_t (independent of recurrence; hides L2 latency)
        float xh0 = out[ob0 + (size_t)t * HDIM];
        float xh1 = out[ob1 + (size_t)t * HDIM];

        u64 acc[4][4];
#pragma unroll
        for (int a = 0; a < 4; a++)
#pragma unroll
            for (int b = 0; b < 4; b++) acc[a][b] = 0ull;

#pragma unroll 4
        for (int s = 0; s < 16; s++) {
            const unsigned kh = (unsigned)(kb4 + s) * 16;
            const unsigned kw = (unsigned)((kb4 + s) ^ xr) * 16;
            u64 h0a,h0b,h1a,h1b,h2a,h2b,h3a,h3b;
            u64 w0a,w0b,w1a,w1b,w2a,w2b,w3a,w3b;
            lds_v2u64(h0a,h0b, hb + 0*2048 + kh);
            lds_v2u64(h1a,h1b, hb + 1*2048 + kh);
            lds_v2u64(h2a,h2b, hb + 2*2048 + kh);
            lds_v2u64(h3a,h3b, hb + 3*2048 + kh);
            lds_v2u64(w0a,w0b, wRow[0] + kw);
            lds_v2u64(w1a,w1b, wRow[1] + kw);
            lds_v2u64(w2a,w2b, wRow[2] + kw);
            lds_v2u64(w3a,w3b, wRow[3] + kw);
            ffma2(acc[0][0],h0a,w0a); ffma2(acc[0][0],h0b,w0b);
            ffma2(acc[0][1],h0a,w1a); ffma2(acc[0][1],h0b,w1b);
            ffma2(acc[0][2],h0a,w2a); ffma2(acc[0][2],h0b,w2b);
            ffma2(acc[0][3],h0a,w3a); ffma2(acc[0][3],h0b,w3b);
            ffma2(acc[1][0],h1a,w0a); ffma2(acc[1][0],h1b,w0b);
            ffma2(acc[1][1],h1a,w1a); ffma2(acc[1][1],h1b,w1b);
            ffma2(acc[1][2],h1a,w2a); ffma2(acc[1][2],h1b,w2b);
            ffma2(acc[1][3],h1a,w3a); ffma2(acc[1][3],h1b,w3b);
            ffma2(acc[2][0],h2a,w0a); ffma2(acc[2][0],h2b,w0b);
            ffma2(acc[2][1],h2a,w1a); ffma2(acc[2][1],h2b,w1b);
            ffma2(acc[2][2],h2a,w2a); ffma2(acc[2][2],h2b,w2b);
            ffma2(acc[2][3],h2a,w3a); ffma2(acc[2][3],h2b,w3b);
            ffma2(acc[3][0],h3a,w0a); ffma2(acc[3][0],h3b,w0b);
            ffma2(acc[3][1],h3a,w1a); ffma2(acc[3][1],h3b,w1b);
            ffma2(acc[3][2],h3a,w2a); ffma2(acc[3][2],h3b,w2b);
            ffma2(acc[3][3],h3a,w3a); ffma2(acc[3][3],h3b,w3b);
        }

        // K-split partials
        float* rp = sm + SOFF_R + kc * (SNB * SJB);
#pragma unroll
        for (int a = 0; a < 4; a++)
#pragma unroll
            for (int b = 0; b < 4; b++)
                rp[a * SJB + jt*4 + b] = hsum2(acc[a][b]);
        __syncthreads();

        // reduce + bias + xh + tanh; write output; push h_t to all cluster CTAs
        float s0 = 0.f, s1 = 0.f;
#pragma unroll
        for (int c = 0; c < 8; c++) {
            s0 += sm[SOFF_R + c * (SNB*SJB) + o0];
            s1 += sm[SOFF_R + c * (SNB*SJB) + o1];
        }
        float v0 = tanhf(s0 + sm[SOFF_B + jj0] + xh0);
        float v1 = tanhf(s1 + sm[SOFF_B + jj1] + xh1);
        out[ob0 + (size_t)t * HDIM] = v0;
        out[ob1 + (size_t)t * HDIM] = v1;

        const unsigned d0 = pb + (unsigned)(nn0 * HDIM + j0 + jj0) * 4;
        const unsigned d1 = pb + (unsigned)(nn1 * HDIM + j0 + jj1) * 4;
#pragma unroll
        for (int r = 0; r < CL; r++) {
            st_cluster_f32(d0, r, v0);
            st_cluster_f32(d1, r, v1);
        }
        CLUSTER_SYNC();   // pushes visible cluster-wide; also acts as CTA barrier
    }
}

// ======================================================================
extern "C" void kernel_launch(void* const* d_in, const int* in_sizes, int n_in,
                              void* d_out, int out_size) {
    const int*   X    = (const int*)d_in[0];
    const float* emb  = (const float*)d_in[1];
    const float* W_hh = (const float*)d_in[2];
    const float* b_hh = (const float*)d_in[3];
    const float* W_xh = (const float*)d_in[4];
    const float* b_xh = (const float*)d_in[5];
    float* out = (float*)d_out;
    (void)in_sizes; (void)n_in; (void)out_size;

    cudaFuncSetAttribute(scan_kernel,
                         cudaFuncAttributeMaxDynamicSharedMemorySize, SSMEM_BYTES);

    dim3 g1(HDIM / 64, (NBATCH * LSEQ) / 64);   // (8, 2048)
    xh_gemm_kernel<<<g1, 256>>>(X, emb, W_xh, b_xh, out);

    scan_kernel<<<16 * CL, ST, SSMEM_BYTES>>>(W_hh, b_hh, out);
}

// round 6
// speedup vs baseline: 1.0691x; 1.0124x over previous
#include <cuda_runtime.h>
#include <math.h>
#include <stdint.h>

#define NBATCH 64
#define LSEQ   2048
#define HDIM   512

typedef unsigned long long u64;

// ---------------------------------------------------------------- helpers
__device__ __forceinline__ void ffma2(u64 &acc, u64 a, u64 b) {
    asm("fma.rn.f32x2 %0, %1, %2, %0;" : "+l"(acc) : "l"(a), "l"(b));
}
__device__ __forceinline__ u64 lds_u64(unsigned addr) {
    u64 v;
    asm volatile("ld.shared.b64 %0, [%1];" : "=l"(v) : "r"(addr));
    return v;
}
__device__ __forceinline__ void lds_v2u64(u64 &a, u64 &b, unsigned addr) {
    asm volatile("ld.shared.v2.b64 {%0,%1}, [%2];" : "=l"(a), "=l"(b) : "r"(addr));
}
__device__ __forceinline__ float hsum2(u64 v) {
    float x, y;
    asm("mov.b64 {%0,%1}, %2;" : "=f"(x), "=f"(y) : "l"(v));
    return x + y;
}
__device__ __forceinline__ unsigned smem_u32(const void* p) {
    unsigned r;
    asm("{ .reg .u64 t; cvta.to.shared.u64 t, %1; cvt.u32.u64 %0, t; }"
        : "=r"(r) : "l"(p));
    return r;
}
__device__ __forceinline__ unsigned mapa_u32(unsigned addr, int rank) {
    unsigned ra;
    asm("mapa.shared::cluster.u32 %0, %1, %2;" : "=r"(ra) : "r"(addr), "r"(rank));
    return ra;
}
__device__ __forceinline__ void st_cluster_f32(unsigned raddr, float v) {
    asm volatile("st.shared::cluster.f32 [%0], %1;" :: "r"(raddr), "f"(v) : "memory");
}
#define CLUSTER_SYNC() do { \
    asm volatile("barrier.cluster.arrive.aligned;" ::: "memory"); \
    asm volatile("barrier.cluster.wait.aligned;"   ::: "memory"); } while (0)

// ======================================================================
// Kernel 1: Xh = emb[X] @ W_xh^T + b_xh  -> out (in place for the scan)
// 64x64 tile, BK=16, 256 threads, STRIDED 4x4 register tile
// (m = ty+16a, j = tx+16b) so every B lds.b64 is 16 lanes x 8B contiguous
// = 1 conflict-free wavefront. f32x2 packed FMA.
// ======================================================================
__global__ __launch_bounds__(256) void xh_gemm_kernel(
    const int* __restrict__ X, const float* __restrict__ emb,
    const float* __restrict__ W_xh, const float* __restrict__ b_xh,
    float* __restrict__ out)
{
    __shared__ __align__(16) float2 As2[8][64];   // [k-pair][m]
    __shared__ __align__(16) float2 Bs2[8][64];   // [k-pair][j]
    const int tid = threadIdx.x;
    const int m0 = blockIdx.y * 64;
    const int j0 = blockIdx.x * 64;
    const int row = tid >> 2;   // 0..63 (loader row)
    const int kq  = tid & 3;    // 0..3  (loader k-quad)
    const int ty  = tid >> 4;   // 0..15
    const int tx  = tid & 15;   // 0..15

    const int tok = X[m0 + row];
    const float* arow = emb  + (size_t)tok        * HDIM + kq * 4;
    const float* brow = W_xh + (size_t)(j0 + row) * HDIM + kq * 4;

    const unsigned aB = smem_u32(As2);
    const unsigned bB = smem_u32(Bs2);

    u64 acc[4][4];
#pragma unroll
    for (int i = 0; i < 4; i++)
#pragma unroll
        for (int j = 0; j < 4; j++) acc[i][j] = 0ull;

    float4 av = *(const float4*)(arow);
    float4 bv = *(const float4*)(brow);

    for (int k0 = 0; k0 < HDIM; k0 += 16) {
        __syncthreads();
        As2[kq*2+0][row] = make_float2(av.x, av.y);
        As2[kq*2+1][row] = make_float2(av.z, av.w);
        Bs2[kq*2+0][row] = make_float2(bv.x, bv.y);
        Bs2[kq*2+1][row] = make_float2(bv.z, bv.w);
        __syncthreads();
        if (k0 + 16 < HDIM) {
            av = *(const float4*)(arow + k0 + 16);
            bv = *(const float4*)(brow + k0 + 16);
        }
#pragma unroll
        for (int kk2 = 0; kk2 < 8; kk2++) {
            u64 a[4], b[4];
#pragma unroll
            for (int i = 0; i < 4; i++)
                a[i] = lds_u64(aB + (unsigned)(kk2*64 + ty + 16*i) * 8);
#pragma unroll
            for (int i = 0; i < 4; i++)
                b[i] = lds_u64(bB + (unsigned)(kk2*64 + tx + 16*i) * 8);
#pragma unroll
            for (int i = 0; i < 4; i++)
#pragma unroll
                for (int j = 0; j < 4; j++)
                    ffma2(acc[i][j], a[i], b[j]);
        }
    }

    float bx[4];
#pragma unroll
    for (int j = 0; j < 4; j++) bx[j] = b_xh[j0 + tx + 16*j];
#pragma unroll
    for (int i = 0; i < 4; i++) {
        float* orow = out + (size_t)(m0 + ty + 16*i) * HDIM + j0 + tx;
#pragma unroll
        for (int j = 0; j < 4; j++)
            orow[16*j] = hsum2(acc[i][j]) + bx[j];
    }
}

// ======================================================================
// Kernel 2: persistent scan. 16 batch-groups (4 rows each), each group =
// an 8-CTA cluster over j (64 j per CTA). 256 threads (2 warps/SMSP) to
// hide LDS latency. h exchange: coalesced st.shared::cluster pushes
// (mapa hoisted out of the loop) + barrier.cluster. Double-buffered h.
// Thread map: kc = warp (8 k-chunks of 64), jt 0..15, nt 0..1;
// 2x4 register tile, f32x2 packed FMA; h rows swizzled conflict-free.
// ======================================================================
#define CL   8
#define SNB  4
#define SJB  64
#define ST   256

// smem float offsets
#define SOFF_W   0                         // 64 x 512 = 32768
#define SOFF_H0  32768                     // 4 x 512
#define SOFF_H1  (SOFF_H0 + SNB*HDIM)      // 4 x 512
#define SOFF_R   (SOFF_H1 + SNB*HDIM)      // 8 x 256 partials
#define SOFF_B   (SOFF_R + 8*SNB*SJB)      // 64 bias
#define SSMEM_FLOATS (SOFF_B + SJB)
#define SSMEM_BYTES  (SSMEM_FLOATS * 4)    // 155,904 B

// W swizzle: float4 index xor by row-block (rows of 4) -> 8 distinct quads
__device__ __forceinline__ int wsw(int r, int k4) { return r*128 + (k4 ^ ((r>>2)&7)); }
// h swizzle: rows 0..3 xor 0,2,4,6 -> distinct 16B quads per row
__device__ __forceinline__ int hswz(int r, int k4) { return r*128 + (k4 ^ (2*r)); }

__global__ __launch_bounds__(ST, 1) __cluster_dims__(CL, 1, 1)
void scan_kernel(const float* __restrict__ W_hh,
                 const float* __restrict__ b_hh, float* __restrict__ out)
{
    extern __shared__ float sm[];
    const unsigned smb = smem_u32(sm);
    const int tid = threadIdx.x;
    int rank;
    asm("mov.u32 %0, %%cluster_ctarank;" : "=r"(rank));
    const int gn = blockIdx.x / CL;        // 0..15 batch-group
    const int n0 = gn * SNB;
    const int j0 = rank * SJB;

    // persistent W_hh slice (rows j0..j0+63), swizzled
    const float4* W4 = (const float4*)W_hh + (size_t)j0 * (HDIM/4);
    float4* smW4 = (float4*)(sm + SOFF_W);
    for (int i = tid; i < SJB * (HDIM/4); i += ST) {
        int r = i >> 7, c4 = i & 127;
        smW4[wsw(r, c4)] = W4[i];
    }
    if (tid < SJB) sm[SOFF_B + tid] = b_hh[j0 + tid];
    // zero h buffer 0 (read at t=0); zero both for safety of swizzled holes
    for (int i = tid; i < 2 * SNB * HDIM; i += ST) sm[SOFF_H0 + i] = 0.f;
    __syncthreads();
    CLUSTER_SYNC();

    // compute mapping: warp = kc (uniform), lanes = jt*2 + nt
    const int kc  = tid >> 5;              // 0..7 k-chunk (64 k)
    const int jt  = (tid >> 1) & 15;       // 0..15 j-tile (4 j)
    const int nt  = tid & 1;               // 0..1  n-half (2 rows)
    const int kb4 = kc * 16;
    const int xr  = jt & 7;

    unsigned wRow[4];
#pragma unroll
    for (int i = 0; i < 4; i++)
        wRow[i] = smb + SOFF_W*4 + (unsigned)(jt*4 + i) * 2048;

    // output ownership: 1 output per thread
    const int o  = tid;
    const int nn = o >> 6, jj = o & 63;
    const size_t ob = (size_t)(n0 + nn) * LSEQ * HDIM + j0 + jj;

    // push target: swizzled float offset of (nn, k = j0+jj) in an h buffer
    const int fidx = nn*128*4 + ((((j0 + jj) >> 2) & 127) ^ (2*nn)) * 4
                   + ((j0 + jj) & 3);
    const unsigned offBuf0 = (unsigned)(SOFF_H0 + fidx) * 4;  // bytes
    // remote smem bases (mapa hoisted; offsets preserved under mapa)
    unsigned rb[CL];
#pragma unroll
    for (int r = 0; r < CL; r++) rb[r] = mapa_u32(smb, r);

    for (int t = 0; t < LSEQ; t++) {
        const unsigned hb = smb + (unsigned)(SOFF_H0 + (t & 1) * (SNB*HDIM)) * 4;
        const unsigned pOff = offBuf0 + (unsigned)(((t & 1) ^ 1) * (SNB*HDIM)) * 4;

        // prefetch xh_t (independent of recurrence)
        float xh = out[ob + (size_t)t * HDIM];

        u64 acc[2][4];
#pragma unroll
        for (int a = 0; a < 2; a++)
#pragma unroll
            for (int b = 0; b < 4; b++) acc[a][b] = 0ull;

#pragma unroll 8
        for (int s = 0; s < 16; s++) {
            const int k4 = kb4 + s;
            u64 h0a,h0b,h1a,h1b;
            u64 w0a,w0b,w1a,w1b,w2a,w2b,w3a,w3b;
            lds_v2u64(h0a,h0b, hb + (unsigned)hswz(nt*2 + 0, k4) * 16);
            lds_v2u64(h1a,h1b, hb + (unsigned)hswz(nt*2 + 1, k4) * 16);
            const unsigned kw = (unsigned)(k4 ^ xr) * 16;
            lds_v2u64(w0a,w0b, wRow[0] + kw);
            lds_v2u64(w1a,w1b, wRow[1] + kw);
            lds_v2u64(w2a,w2b, wRow[2] + kw);
            lds_v2u64(w3a,w3b, wRow[3] + kw);
            ffma2(acc[0][0],h0a,w0a); ffma2(acc[0][0],h0b,w0b);
            ffma2(acc[0][1],h0a,w1a); ffma2(acc[0][1],h0b,w1b);
            ffma2(acc[0][2],h0a,w2a); ffma2(acc[0][2],h0b,w2b);
            ffma2(acc[0][3],h0a,w3a); ffma2(acc[0][3],h0b,w3b);
            ffma2(acc[1][0],h1a,w0a); ffma2(acc[1][0],h1b,w0b);
            ffma2(acc[1][1],h1a,w1a); ffma2(acc[1][1],h1b,w1b);
            ffma2(acc[1][2],h1a,w2a); ffma2(acc[1][2],h1b,w2b);
            ffma2(acc[1][3],h1a,w3a); ffma2(acc[1][3],h1b,w3b);
        }

        // K-split partials: [kc][nn*64 + jj]
        float* rp = sm + SOFF_R + kc * (SNB * SJB);
#pragma unroll
        for (int a = 0; a < 2; a++)
#pragma unroll
            for (int b = 0; b < 4; b++)
                rp[(nt*2 + a) * SJB + jt*4 + b] = hsum2(acc[a][b]);
        __syncthreads();

        // reduce + bias + xh + tanh
        float s = 0.f;
#pragma unroll
        for (int c = 0; c < 8; c++) s += sm[SOFF_R + c * (SNB*SJB) + o];
        float v = tanhf(s + sm[SOFF_B + jj] + xh);

        // push h_t to every cluster CTA (coalesced 128B wavefronts/rank)
#pragma unroll
        for (int r = 0; r < CL; r++) st_cluster_f32(rb[r] + pOff, v);

        out[ob + (size_t)t * HDIM] = v;   // gmem store off critical path

        CLUSTER_SYNC();   // pushes visible cluster-wide; also CTA barrier
    }
}

// ======================================================================
extern "C" void kernel_launch(void* const* d_in, const int* in_sizes, int n_in,
                              void* d_out, int out_size) {
    const int*   X    = (const int*)d_in[0];
    const float* emb  = (const float*)d_in[1];
    const float* W_hh = (const float*)d_in[2];
    const float* b_hh = (const float*)d_in[3];
    const float* W_xh = (const float*)d_in[4];
    const float* b_xh = (const float*)d_in[5];
    float* out = (float*)d_out;
    (void)in_sizes; (void)n_in; (void)out_size;

    cudaFuncSetAttribute(scan_kernel,
                         cudaFuncAttributeMaxDynamicSharedMemorySize, SSMEM_BYTES);

    dim3 g1(HDIM / 64, (NBATCH * LSEQ) / 64);   // (8, 2048)
    xh_gemm_kernel<<<g1, 256>>>(X, emb, W_xh, b_xh, out);

    scan_kernel<<<16 * CL, ST, SSMEM_BYTES>>>(W_hh, b_hh, out);
}

// round 12
// speedup vs baseline: 1.1358x; 1.0624x over previous
#include <cuda_runtime.h>
#include <math.h>
#include <stdint.h>

#define NBATCH 64
#define LSEQ   2048
#define HDIM   512

typedef unsigned long long u64;

// ---------------------------------------------------------------- helpers
__device__ __forceinline__ void ffma2(u64 &acc, u64 a, u64 b) {
    asm("fma.rn.f32x2 %0, %1, %2, %0;" : "+l"(acc) : "l"(a), "l"(b));
}
__device__ __forceinline__ u64 lds_u64(unsigned addr) {
    u64 v;
    asm volatile("ld.shared.b64 %0, [%1];" : "=l"(v) : "r"(addr));
    return v;
}
__device__ __forceinline__ float hsum2(u64 v) {
    float x, y;
    asm("mov.b64 {%0,%1}, %2;" : "=f"(x), "=f"(y) : "l"(v));
    return x + y;
}
__device__ __forceinline__ unsigned smem_u32(const void* p) {
    unsigned r;
    asm("{ .reg .u64 t; cvta.to.shared.u64 t, %1; cvt.u32.u64 %0, t; }"
        : "=r"(r) : "l"(p));
    return r;
}
__device__ __forceinline__ unsigned mapa_u32(unsigned addr, int rank) {
    unsigned ra;
    asm("mapa.shared::cluster.u32 %0, %1, %2;" : "=r"(ra) : "r"(addr), "r"(rank));
    return ra;
}
__device__ __forceinline__ void st_cluster_v2f32(unsigned raddr, float a, float b) {
    asm volatile("st.shared::cluster.v2.f32 [%0], {%1,%2};"
                 :: "r"(raddr), "f"(a), "f"(b) : "memory");
}
// Cluster-scope release ordering for the preceding st.shared::cluster
// stores, then a PLAIN remote arrive (the examples-proven form from
// ptx_helpers MBARRIER_ARRIVE_CLUSTER). fence.acq_rel.cluster +
// arrive-at-the-waited-location == release edge the consumer's
// try_wait.parity.acquire.cluster pairs with. (R7's 0.33 rel_err came
// from the default cta-scope release leaving remote stores unordered.)
__device__ __forceinline__ void fence_acqrel_cluster() {
    asm volatile("fence.acq_rel.cluster;" ::: "memory");
}
__device__ __forceinline__ void mbar_arrive_cluster(unsigned raddr) {
    asm volatile("mbarrier.arrive.shared::cluster.b64 _, [%0];"
                 :: "r"(raddr) : "memory");
}
__device__ __forceinline__ void mbar_init(unsigned addr, unsigned cnt) {
    asm volatile("mbarrier.init.shared.b64 [%0], %1;" :: "r"(addr), "r"(cnt) : "memory");
}
__device__ __forceinline__ void mbar_wait_parity(unsigned addr, unsigned parity) {
    asm volatile(
        "{\n\t"
        ".reg .pred P;\n\t"
        "WL_%=:\n\t"
        "mbarrier.try_wait.parity.acquire.cluster.shared::cta.b64 P, [%0], %1, 0x989680;\n\t"
        "@!P bra WL_%=;\n\t"
        "}"
        :: "r"(addr), "r"(parity) : "memory");
}
#define CLUSTER_SYNC() do { \
    asm volatile("barrier.cluster.arrive.aligned;" ::: "memory"); \
    asm volatile("barrier.cluster.wait.aligned;"   ::: "memory"); } while (0)

// ======================================================================
// Kernel 1: Xh = emb[X] @ W_xh^T + b_xh  -> out (in place for the scan)
// (unchanged: measured ~1.8 ms, conflict-free strided tile + f32x2)
// ======================================================================
__global__ __launch_bounds__(256) void xh_gemm_kernel(
    const int* __restrict__ X, const float* __restrict__ emb,
    const float* __restrict__ W_xh, const float* __restrict__ b_xh,
    float* __restrict__ out)
{
    __shared__ __align__(16) float2 As2[8][64];
    __shared__ __align__(16) float2 Bs2[8][64];
    const int tid = threadIdx.x;
    const int m0 = blockIdx.y * 64;
    const int j0 = blockIdx.x * 64;
    const int row = tid >> 2;
    const int kq  = tid & 3;
    const int ty  = tid >> 4;
    const int tx  = tid & 15;

    const int tok = X[m0 + row];
    const float* arow = emb  + (size_t)tok        * HDIM + kq * 4;
    const float* brow = W_xh + (size_t)(j0 + row) * HDIM + kq * 4;

    const unsigned aB = smem_u32(As2);
    const unsigned bB = smem_u32(Bs2);

    u64 acc[4][4];
#pragma unroll
    for (int i = 0; i < 4; i++)
#pragma unroll
        for (int j = 0; j < 4; j++) acc[i][j] = 0ull;

    float4 av = *(const float4*)(arow);
    float4 bv = *(const float4*)(brow);

    for (int k0 = 0; k0 < HDIM; k0 += 16) {
        __syncthreads();
        As2[kq*2+0][row] = make_float2(av.x, av.y);
        As2[kq*2+1][row] = make_float2(av.z, av.w);
        Bs2[kq*2+0][row] = make_float2(bv.x, bv.y);
        Bs2[kq*2+1][row] = make_float2(bv.z, bv.w);
        __syncthreads();
        if (k0 + 16 < HDIM) {
            av = *(const float4*)(arow + k0 + 16);
            bv = *(const float4*)(brow + k0 + 16);
        }
#pragma unroll
        for (int kk2 = 0; kk2 < 8; kk2++) {
            u64 a[4], b[4];
#pragma unroll
            for (int i = 0; i < 4; i++)
                a[i] = lds_u64(aB + (unsigned)(kk2*64 + ty + 16*i) * 8);
#pragma unroll
            for (int i = 0; i < 4; i++)
                b[i] = lds_u64(bB + (unsigned)(kk2*64 + tx + 16*i) * 8);
#pragma unroll
            for (int i = 0; i < 4; i++)
#pragma unroll
                for (int j = 0; j < 4; j++)
                    ffma2(acc[i][j], a[i], b[j]);
        }
    }

    float bx[4];
#pragma unroll
    for (int j = 0; j < 4; j++) bx[j] = b_xh[j0 + tx + 16*j];
#pragma unroll
    for (int i = 0; i < 4; i++) {
        float* orow = out + (size_t)(m0 + ty + 16*i) * HDIM + j0 + tx;
#pragma unroll
        for (int j = 0; j < 4; j++)
            orow[16*j] = hsum2(acc[i][j]) + bx[j];
    }
}

// ======================================================================
// Kernel 2: persistent scan, LOCAL-K decomposition.
// 16 batch-groups (4 rows) x 8-CTA clusters over j (64 j / CTA).
// Per iter t: each CTA computes z[512][4] = W_hh[:, own 64 cols] x own
// h chunk (LOCAL — no wait), pushes per-slice partials to owners'
// double-buffered smem, fence.acq_rel.cluster, arrives on owners'
// mbarrier; owner waits its local mbarrier (acquire.cluster), sums 8
// partials, + bias + xh, tanh -> new own h chunk. NO cluster-wide
// barrier in loop. 128 threads (warp w serves slices 2w, 2w+1).
// ======================================================================
#define CL   8
#define SNB  4
#define ST2  128

// smem float offsets
#define OFF_W2   0                        // 512 rows x 32 u64  = 32768 floats (128KB)
#define OFF_H    32768                    // h own chunk [n][k] = 256 floats
#define OFF_P    (OFF_H + 256)            // partials [2][8][256] = 4096 floats
#define OFF_BIAS (OFF_P + 4096)           // 64
#define OFF_MBAR (OFF_BIAS + 64)          // 2 x u64 (4 floats, 8B aligned)
#define SC_FLOATS (OFF_MBAR + 4)
#define SC_BYTES  (SC_FLOATS * 4)         // 149,008 B

__global__ __launch_bounds__(ST2, 1) __cluster_dims__(CL, 1, 1)
void scan_kernel(const float* __restrict__ W_hh,
                 const float* __restrict__ b_hh, float* __restrict__ out)
{
    extern __shared__ float sm[];
    const unsigned smb = smem_u32(sm);
    const int tid = threadIdx.x;
    int rank;
    asm("mov.u32 %0, %%cluster_ctarank;" : "=r"(rank));
    const int gn = blockIdx.x / CL;        // 0..15 batch-group
    const int n0 = gn * SNB;
    const int j0 = rank * 64;              // my j-slice = my k-chunk

    // ---- stage W2[j][kp] = {W_hh[j][j0+2kp], W_hh[j][j0+2kp+1]},
    //      swizzled: slot = kp ^ ((j>>1)&31)   (conflict-free compute loads)
    u64* W2 = (u64*)(sm + OFF_W2);
    const float* Wg = W_hh;
    for (int idx = tid; idx < 512 * 32; idx += ST2) {
        int j = idx >> 5, kp = idx & 31;
        float a = Wg[(size_t)j * HDIM + j0 + 2*kp];
        float b = Wg[(size_t)j * HDIM + j0 + 2*kp + 1];
        u64 v;
        asm("mov.b64 %0, {%1,%2};" : "=l"(v) : "f"(a), "f"(b));
        W2[(j << 5) | (kp ^ ((j >> 1) & 31))] = v;
    }
    if (tid < 64) sm[OFF_BIAS + tid] = b_hh[j0 + tid];
    // h_{-1} = 0
    for (int i = tid; i < 256; i += ST2) sm[OFF_H + i] = 0.f;
    if (tid == 0) {
        mbar_init(smb + OFF_MBAR*4,     CL * 32);   // 256 arrivals
        mbar_init(smb + OFF_MBAR*4 + 8, CL * 32);
    }
    __syncthreads();
    CLUSTER_SYNC();   // peers must see mbar init + (own) buffers ready

    const int w = tid >> 5;                // warp 0..3 -> slices 2w, 2w+1
    const int l = tid & 31;

    // W row byte addrs: j = s*64 + 2l + jl, s in {2w, 2w+1}; xor term = l
    unsigned wA[2][2];
#pragma unroll
    for (int si = 0; si < 2; si++)
#pragma unroll
        for (int jl = 0; jl < 2; jl++)
            wA[si][jl] = smb + (unsigned)(OFF_W2*4)
                       + (unsigned)(((2*w + si)*64 + 2*l + jl) * 32) * 8;
    const unsigned hA = smb + OFF_H * 4;

    // remote bases for my two destination ranks (mapa hoisted)
    unsigned rb[2];
#pragma unroll
    for (int si = 0; si < 2; si++) rb[si] = mapa_u32(smb, 2*w + si);

    // reduce/output ownership: outputs o = tid, tid+128; o = n*64 + jj
    const int o0 = tid, o1 = tid + ST2;
    const size_t ga0 = (size_t)(n0 + (o0 >> 6)) * LSEQ * HDIM + j0 + (o0 & 63);
    const size_t ga1 = (size_t)(n0 + (o1 >> 6)) * LSEQ * HDIM + j0 + (o1 & 63);

    for (int t = 0; t < LSEQ; t++) {
        const unsigned ph  = (unsigned)(t & 1);
        // prefetch xh_t
        float xh0 = out[ga0 + (size_t)t * HDIM];
        float xh1 = out[ga1 + (size_t)t * HDIM];

        // ---- compute z for slices 2w, 2w+1 from OWN h chunk (local) ----
        u64 acc[2][2][4];   // [si][jl][n], packed over k
#pragma unroll
        for (int si = 0; si < 2; si++)
#pragma unroll
            for (int jl = 0; jl < 2; jl++)
#pragma unroll
                for (int n = 0; n < 4; n++) acc[si][jl][n] = 0ull;

#pragma unroll 8
        for (int kp = 0; kp < 32; kp++) {
            const unsigned wk = (unsigned)((kp ^ l) * 8);
            u64 wv[2][2];
#pragma unroll
            for (int si = 0; si < 2; si++)
#pragma unroll
                for (int jl = 0; jl < 2; jl++)
                    wv[si][jl] = lds_u64(wA[si][jl] + wk);
            u64 hv[4];
#pragma unroll
            for (int n = 0; n < 4; n++)
                hv[n] = lds_u64(hA + (unsigned)(n*256 + kp*8));   // broadcast
#pragma unroll
            for (int si = 0; si < 2; si++)
#pragma unroll
                for (int jl = 0; jl < 2; jl++)
#pragma unroll
                    for (int n = 0; n < 4; n++)
                        ffma2(acc[si][jl][n], wv[si][jl], hv[n]);
        }

        // ---- push ALL partials, one release fence, then both arrives ----
        const unsigned pOfs = (unsigned)((OFF_P + (ph*8 + rank)*256) * 4);
#pragma unroll
        for (int si = 0; si < 2; si++)
#pragma unroll
            for (int n = 0; n < 4; n++) {
                float za = hsum2(acc[si][0][n]);
                float zb = hsum2(acc[si][1][n]);
                st_cluster_v2f32(rb[si] + pOfs + (unsigned)((n*64 + 2*l)*4), za, zb);
            }
        fence_acqrel_cluster();   // cluster-scope release of the stores above
#pragma unroll
        for (int si = 0; si < 2; si++)
            mbar_arrive_cluster(rb[si] + (unsigned)(OFF_MBAR*4) + ph*8);
        __syncthreads();   // all warps done reading hbuf before overwrite

        // ---- wait for all 8 sources, then reduce + tanh -> new h chunk ----
        mbar_wait_parity(smb + OFF_MBAR*4 + ph*8, (unsigned)((t >> 1) & 1));

        const float* pb = sm + OFF_P + ph * 2048;
        float s0 = 0.f, s1 = 0.f;
#pragma unroll
        for (int c = 0; c < 8; c++) {
            s0 += pb[c*256 + o0];
            s1 += pb[c*256 + o1];
        }
        float v0 = tanhf(s0 + sm[OFF_BIAS + (o0 & 63)] + xh0);
        float v1 = tanhf(s1 + sm[OFF_BIAS + (o1 & 63)] + xh1);
        sm[OFF_H + o0] = v0;
        sm[OFF_H + o1] = v1;
        out[ga0 + (size_t)t * HDIM] = v0;
        out[ga1 + (size_t)t * HDIM] = v1;
        __syncthreads();   // h chunk complete before next compute
    }

    CLUSTER_SYNC();   // keep smem alive until all peers consumed everything
}

// ======================================================================
extern "C" void kernel_launch(void* const* d_in, const int* in_sizes, int n_in,
                              void* d_out, int out_size) {
    const int*   X    = (const int*)d_in[0];
    const float* emb  = (const float*)d_in[1];
    const float* W_hh = (const float*)d_in[2];
    const float* b_hh = (const float*)d_in[3];
    const float* W_xh = (const float*)d_in[4];
    const float* b_xh = (const float*)d_in[5];
    float* out = (float*)d_out;
    (void)in_sizes; (void)n_in; (void)out_size;

    cudaFuncSetAttribute(scan_kernel,
                         cudaFuncAttributeMaxDynamicSharedMemorySize, SC_BYTES);

    dim3 g1(HDIM / 64, (NBATCH * LSEQ) / 64);   // (8, 2048)
    xh_gemm_kernel<<<g1, 256>>>(X, emb, W_xh, b_xh, out);

    scan_kernel<<<16 * CL, ST2, SC_BYTES>>>(W_hh, b_hh, out);
}